// round 3
// baseline (speedup 1.0000x reference)
#include <cuda_runtime.h>
#include <math.h>

#define Bv  4
#define Nn  24
#define NTT 16
#define TSS 48
#define TT  64
#define THR 384
#define NL  (Nn - 1)   // 23 l-slots per batch

// ---------------- device scratch ----------------
__device__ float d_E0t [Bv][Nn][NTT][NTT][NTT];      // exp(R0[a,h,s<16,c<16]) as [b][h][s][c][a]
__device__ float d_E1t [Bv][Nn][NTT][NTT][NTT];
__device__ float d_U0t [Bv][Nn][Nn][NTT][NTT];       // [b][h][k][s][a]
__device__ float d_U1t [Bv][Nn][Nn][NTT][NTT];       // [b][h][k][c][a]
__device__ float d_V0t [Bv][Nn][TT][NTT];            // [b][h][c][a]
__device__ float d_V1t [Bv][Nn][TT][NTT];            // [b][h][s][a]
__device__ float d_beta [Bv][Nn+1][Nn+1][NTT][Nn];
__device__ float d_betau[Bv][Nn+1][Nn+1][NTT];
__device__ float d_Ssc  [Bv][Nn+1][Nn+1];
__device__ volatile unsigned d_flag[Bv][Nn+1][Nn+1];

// ---------------- kernel 1: rule precompute (block per (b,a,h)) + flag reset ----------------
__global__ void __launch_bounds__(256) k_pre(const float* __restrict__ rule,
                                             const float* __restrict__ unary) {
    int blk = blockIdx.x;
    int h = blk % Nn;
    int a = (blk / Nn) % NTT;
    int b = blk / (Nn * NTT);
    const float2* R2 = (const float2*)(rule + (size_t)((b * NTT + a) * Nn + h) * (TT * TT * 2));

    __shared__ float Er0[TT][TT];
    __shared__ float Er1[TT][TT];
    __shared__ float eus[Nn][49];
    int tid = threadIdx.x;

    if (blk == 0) {  // reset dataflow flags for this graph replay
        for (int i = tid; i < Bv * (Nn + 1) * (Nn + 1); i += 256)
            ((unsigned*)d_flag)[i] = 0;
    }

    for (int e = tid; e < TT * TT; e += 256) {
        float2 v = R2[e];
        int s = e >> 6, c = e & 63;
        Er0[s][c] = __expf(v.x);
        Er1[s][c] = __expf(v.y);
    }
    for (int t = tid; t < Nn * TSS; t += 256) {
        int k = t / TSS, c = t % TSS;
        eus[k][c] = __expf(unary[(b * Nn + k) * TT + NTT + c]);
    }
    __syncthreads();

    // E tables (NT x NT corner)
    {
        int s = tid >> 4, c = tid & 15;
        d_E0t[b][h][s][c][a] = Er0[s][c];
        d_E1t[b][h][s][c][a] = Er1[s][c];
    }
    // V tables
    if (tid < 128) {
        int x = tid & 63;
        float acc = 0.f;
        if (tid < 64) {
            #pragma unroll 8
            for (int s = NTT; s < TT; s++) acc += Er0[s][x];
            d_V0t[b][h][x][a] = acc;
        } else {
            #pragma unroll 8
            for (int c = NTT; c < TT; c++) acc += Er1[x][c];
            d_V1t[b][h][x][a] = acc;
        }
    }
    // U tables, register-tiled 4x over k
    if (tid < 192) {
        int which = tid / 96;
        int g = tid % 96;
        int x = g & 15, k0 = (g >> 4) * 4;
        float a0 = 0.f, a1 = 0.f, a2 = 0.f, a3 = 0.f;
        if (which == 0) {
            #pragma unroll 8
            for (int c = 0; c < TSS; c++) {
                float e = Er0[x][NTT + c];
                a0 += e * eus[k0 + 0][c];
                a1 += e * eus[k0 + 1][c];
                a2 += e * eus[k0 + 2][c];
                a3 += e * eus[k0 + 3][c];
            }
            d_U0t[b][h][k0 + 0][x][a] = a0;
            d_U0t[b][h][k0 + 1][x][a] = a1;
            d_U0t[b][h][k0 + 2][x][a] = a2;
            d_U0t[b][h][k0 + 3][x][a] = a3;
        } else {
            #pragma unroll 8
            for (int s = 0; s < TSS; s++) {
                float e = Er1[NTT + s][x];
                a0 += e * eus[k0 + 0][s];
                a1 += e * eus[k0 + 1][s];
                a2 += e * eus[k0 + 2][s];
                a3 += e * eus[k0 + 3][s];
            }
            d_U1t[b][h][k0 + 0][x][a] = a0;
            d_U1t[b][h][k0 + 1][x][a] = a1;
            d_U1t[b][h][k0 + 2][x][a] = a2;
            d_U1t[b][h][k0 + 3][x][a] = a3;
        }
    }
}

// ---------------- kernel 2: dataflow chart kernel ----------------
__global__ void __launch_bounds__(THR, 1) k_chart(const float* __restrict__ unary,
                                                  const float* __restrict__ root,
                                                  float* __restrict__ out) {
    extern __shared__ float Psm[];   // [2][256][W]
    __shared__ float eu_s[Nn][TT];
    __shared__ float buR[Nn][NTT];
    __shared__ float buL[Nn][NTT];
    __shared__ float BL2[NTT][Nn];
    __shared__ float BL3[NTT][Nn];
    __shared__ float wsp[Nn];
    __shared__ float tmpsm[NTT][Nn];
    __shared__ float Ppart[4][Nn][NTT];
    __shared__ float red[12];
    __shared__ float sref_s, Msm;

    int tid = threadIdx.x;
    int b = blockIdx.x / NL;
    int l = blockIdx.x % NL;

    // per-batch exp(unary) into smem
    for (int t = tid; t < Nn * TT; t += THR)
        (&eu_s[0][0])[t] = __expf(unary[b * Nn * TT + t]);
    __syncthreads();

    int Wmax = Nn - l;
    for (int W = 2; W <= Wmax; W++) {
        int r = l + W;
        int nT = NTT * W;

        // ---- wait for right-edge children (m, r), m = l+1 .. r-2 ----
        if (W >= 3 && tid <= W - 3) {
            while (d_flag[b][l + 1 + tid][r] == 0) __nanosleep(32);
            __threadfence();   // acquire
        }
        __syncthreads();

        // ---- split-scale weights ----
        if (tid < W - 1) {
            int j = tid, m = l + 1 + j;
            float sl = (j == 0)     ? 0.f : __ldcg(&d_Ssc[b][l][m]);
            float sr = (j == W - 2) ? 0.f : __ldcg(&d_Ssc[b][m][r]);
            wsp[j] = sl + sr;
        }
        __syncthreads();
        if (tid == 0) {
            float s = -1e30f;
            for (int j = 0; j <= W - 2; j++) s = fmaxf(s, wsp[j]);
            sref_s = s;
        }
        __syncthreads();
        if (tid < W - 1) wsp[tid] = __expf(wsp[tid] - sref_s);
        __syncthreads();

        // ---- child charts into smem ----
        if (W >= 3) {
            if (tid < (W - 2) * NTT) {
                int j = tid >> 4, c = tid & 15;
                buR[j][c]     = wsp[j]     * __ldcg(&d_betau[b][l + 1 + j][r][c]);
                buL[j + 1][c] = wsp[j + 1] * __ldcg(&d_betau[b][l][l + 2 + j][c]);
            }
            if (tid < nT) {
                int c = tid / W, hh = tid % W;
                BL2[c][hh] = __ldcg(&d_beta[b][l + 1][r][c][l + hh]);
                BL3[c][hh] = __ldcg(&d_beta[b][l][r - 1][c][l + hh]);
            }
        }
        __syncthreads();

        float tacc = 0.f;
        float* P0 = Psm;
        float* P1 = Psm + 256 * W;

        if (W >= 4) {
            // ---- build P0/P1 with span-tightened j ranges and chunk-4 prefetch ----
            if (tid < nT) {
                int hh = tid % W, x = tid / W;
                float av[NTT];
                // P0: head in left child -> j >= hh
                #pragma unroll
                for (int c = 0; c < NTT; c++) av[c] = 0.f;
                {
                    int j = (hh > 1) ? hh : 1;
                    for (; j + 3 <= W - 3; j += 4) {
                        float b0 = __ldcg(&d_beta[b][l][l + 1 + j][x][l + hh]);
                        float b1 = __ldcg(&d_beta[b][l][l + 2 + j][x][l + hh]);
                        float b2 = __ldcg(&d_beta[b][l][l + 3 + j][x][l + hh]);
                        float b3 = __ldcg(&d_beta[b][l][l + 4 + j][x][l + hh]);
                        #pragma unroll
                        for (int c = 0; c < NTT; c++) {
                            av[c] += b0 * buR[j][c];
                            av[c] += b1 * buR[j + 1][c];
                            av[c] += b2 * buR[j + 2][c];
                            av[c] += b3 * buR[j + 3][c];
                        }
                    }
                    for (; j <= W - 3; j++) {
                        float bl = __ldcg(&d_beta[b][l][l + 1 + j][x][l + hh]);
                        #pragma unroll
                        for (int c = 0; c < NTT; c++) av[c] += bl * buR[j][c];
                    }
                }
                #pragma unroll
                for (int c = 0; c < NTT; c++) P0[(x * NTT + c) * W + hh] = av[c];
                // P1: head in right child -> j <= hh-1
                #pragma unroll
                for (int c = 0; c < NTT; c++) av[c] = 0.f;
                {
                    int jend = hh - 1; if (jend > W - 3) jend = W - 3;
                    int j = 1;
                    for (; j + 3 <= jend; j += 4) {
                        float b0 = __ldcg(&d_beta[b][l + 1 + j][r][x][l + hh]);
                        float b1 = __ldcg(&d_beta[b][l + 2 + j][r][x][l + hh]);
                        float b2 = __ldcg(&d_beta[b][l + 3 + j][r][x][l + hh]);
                        float b3 = __ldcg(&d_beta[b][l + 4 + j][r][x][l + hh]);
                        #pragma unroll
                        for (int c = 0; c < NTT; c++) {
                            av[c] += b0 * buL[j][c];
                            av[c] += b1 * buL[j + 1][c];
                            av[c] += b2 * buL[j + 2][c];
                            av[c] += b3 * buL[j + 3][c];
                        }
                    }
                    for (; j <= jend; j++) {
                        float br = __ldcg(&d_beta[b][l + 1 + j][r][x][l + hh]);
                        #pragma unroll
                        for (int c = 0; c < NTT; c++) av[c] += br * buL[j][c];
                    }
                }
                #pragma unroll
                for (int c = 0; c < NTT; c++) P1[(c * NTT + x) * W + hh] = av[c];
            }
            __syncthreads();

            // ---- dual contraction, float4 over a, 4-way sc split ----
            if (tid < nT) {
                int part = tid / (4 * W);
                int rem  = tid - part * 4 * W;
                int a4 = rem / W;
                int hh = rem - a4 * W;
                const float4* E0 = reinterpret_cast<const float4*>(d_E0t[b][l + hh][0][0]);
                const float4* E1 = reinterpret_cast<const float4*>(d_E1t[b][l + hh][0][0]);
                const float* p0 = P0 + hh;
                const float* p1 = P1 + hh;
                int base = part * 64;
                float4 acc0 = make_float4(0.f, 0.f, 0.f, 0.f);
                float4 acc1 = make_float4(0.f, 0.f, 0.f, 0.f);
                #pragma unroll 4
                for (int i = 0; i < 64; i++) {
                    int sc = base + i;
                    float v0 = p0[sc * W];
                    float v1 = p1[sc * W];
                    float4 e0 = E0[sc * 4 + a4];
                    float4 e1 = E1[sc * 4 + a4];
                    acc0.x += v0 * e0.x; acc0.y += v0 * e0.y;
                    acc0.z += v0 * e0.z; acc0.w += v0 * e0.w;
                    acc1.x += v1 * e1.x; acc1.y += v1 * e1.y;
                    acc1.z += v1 * e1.z; acc1.w += v1 * e1.w;
                }
                Ppart[part][hh][a4 * 4 + 0] = acc0.x + acc1.x;
                Ppart[part][hh][a4 * 4 + 1] = acc0.y + acc1.y;
                Ppart[part][hh][a4 * 4 + 2] = acc0.z + acc1.z;
                Ppart[part][hh][a4 * 4 + 3] = acc0.w + acc1.w;
            }
            __syncthreads();
            if (tid < nT) {
                int a = tid & 15, hh = tid >> 4;
                tacc += Ppart[0][hh][a] + Ppart[1][hh][a] + Ppart[2][hh][a] + Ppart[3][hh][a];
            }
        }

        // ---- boundary (width-1 child) terms ----
        if (W >= 3) {
            if (tid < nT) {
                int a = tid & 15, hh = tid >> 4;
                const float* U1 = &d_U1t[b][l + hh][l][0][a];
                const float* U0 = &d_U0t[b][l + hh][r - 1][0][a];
                float s2 = 0.f, s3 = 0.f;
                #pragma unroll
                for (int c = 0; c < NTT; c++) {
                    s2 += __ldg(U1 + c * NTT) * BL2[c][hh];
                    s3 += __ldg(U0 + c * NTT) * BL3[c][hh];
                }
                tacc += wsp[0] * s2 + wsp[W - 2] * s3;
                if (hh == 0) {
                    float s1 = 0.f;
                    #pragma unroll
                    for (int c = 0; c < NTT; c++)
                        s1 += __ldg(&d_V0t[b][l][c][a]) * buR[0][c];
                    tacc += s1;
                }
                if (hh == W - 1) {
                    float s4 = 0.f;
                    #pragma unroll
                    for (int c = 0; c < NTT; c++)
                        s4 += __ldg(&d_V1t[b][r - 1][c][a]) * buL[W - 2][c];
                    tacc += s4;
                }
            }
        } else {  // W == 2
            if (tid < nT) {
                int a = tid & 15, hh = tid >> 4;
                float acc = 0.f;
                if (hh == 0) {
                    #pragma unroll 8
                    for (int c = 0; c < TSS; c++)
                        acc += eu_s[l + 1][NTT + c] * __ldg(&d_V0t[b][l][NTT + c][a]);
                } else {
                    #pragma unroll 8
                    for (int c = 0; c < TSS; c++)
                        acc += eu_s[l][NTT + c] * __ldg(&d_V1t[b][l + 1][NTT + c][a]);
                }
                tacc += acc;
            }
        }

        // ---- max, rescale, commit, publish ----
        float vmax = 0.f;
        if (tid < nT) {
            int a = tid & 15, hh = tid >> 4;
            tmpsm[a][hh] = tacc;
            vmax = tacc;
        }
        #pragma unroll
        for (int o = 16; o > 0; o >>= 1) vmax = fmaxf(vmax, __shfl_xor_sync(0xffffffffu, vmax, o));
        if ((tid & 31) == 0) red[tid >> 5] = vmax;
        __syncthreads();
        if (tid < 32) {
            float v = (tid < 12) ? red[tid] : 0.f;
            #pragma unroll
            for (int o = 8; o > 0; o >>= 1) v = fmaxf(v, __shfl_xor_sync(0xffffffffu, v, o));
            if (tid == 0) { Msm = v; __stcg(&d_Ssc[b][l][r], sref_s + logf(v)); }
        }
        __syncthreads();
        float invM = 1.f / Msm;
        {
            int a = tid / Nn, habs = tid % Nn;   // THR == 16*24 exactly
            float v = 0.f;
            if (habs >= l && habs < r) v = tmpsm[a][habs - l] * invM;
            __stcg(&d_beta[b][l][r][a][habs], v);
        }
        if (tid < NTT) {
            float accu = 0.f;
            for (int hh = 0; hh < W; hh++)
                accu += tmpsm[tid][hh] * eu_s[l + hh][tid];
            __stcg(&d_betau[b][l][r][tid], accu * invM);
        }
        __threadfence();   // release (per-thread: covers this thread's stores)
        __syncthreads();
        if (tid == 0) d_flag[b][l][r] = 1;
    }

    // ---- root reduction (block (b, 0) computed (0, Nn) last) ----
    if (l == 0 && tid < NTT) {
        float v = __ldcg(&d_betau[b][0][Nn][tid]) * __expf(root[b * NTT + tid]);
        #pragma unroll
        for (int o = 8; o > 0; o >>= 1) v += __shfl_xor_sync(0xffffu, v, o);
        if (tid == 0) out[b] = __ldcg(&d_Ssc[b][0][Nn]) + logf(v);
    }
}

// ---------------- launch ----------------
extern "C" void kernel_launch(void* const* d_in, const int* in_sizes, int n_in,
                              void* d_out, int out_size) {
    const float* unary = nullptr;
    const float* rule  = nullptr;
    const float* root  = nullptr;
    for (int i = 0; i < n_in; i++) {
        if (in_sizes[i] == Bv * Nn * TT)                      unary = (const float*)d_in[i];
        else if (in_sizes[i] == Bv * NTT * Nn * TT * TT * 2)  rule  = (const float*)d_in[i];
        else if (in_sizes[i] == Bv * NTT)                     root  = (const float*)d_in[i];
    }

    cudaFuncSetAttribute(k_chart, cudaFuncAttributeMaxDynamicSharedMemorySize, 49152);

    k_pre<<<Bv * NTT * Nn, 256>>>(rule, unary);
    k_chart<<<Bv * NL, THR, 2 * 256 * Nn * sizeof(float)>>>(unary, root, (float*)d_out);
}

// round 4
// speedup vs baseline: 1.0333x; 1.0333x over previous
#include <cuda_runtime.h>
#include <math.h>

#define Bv  4
#define Nn  24
#define NTT 16
#define TSS 48
#define TT  64
#define THR 384
#define NL  (Nn - 1)          // 23 l-slots per batch
#define GBLK (Bv * NL)        // 92 persistent blocks

// ---------------- device scratch ----------------
__device__ float d_E0t [Bv][Nn][NTT][NTT][NTT];      // exp(R0) as [b][h][s][c][a]
__device__ float d_E1t [Bv][Nn][NTT][NTT][NTT];
__device__ float d_U0t [Bv][Nn][Nn][NTT][NTT];       // [b][h][k][s][a]
__device__ float d_U1t [Bv][Nn][Nn][NTT][NTT];       // [b][h][k][c][a]
__device__ float d_V0t [Bv][Nn][TT][NTT];            // [b][h][c][a]
__device__ float d_V1t [Bv][Nn][TT][NTT];            // [b][h][s][a]
__device__ float d_beta [Bv][Nn+1][Nn+1][NTT][Nn];
__device__ float d_betau[Bv][Nn+1][Nn+1][NTT];
__device__ float d_Ssc  [Bv][Nn+1][Nn+1];
__device__ int           g_cnt;                       // zero-init; self-consistent across replays
__device__ volatile int  g_gen;

// ---------------- kernel 1: rule precompute (block per (b,a,h)) ----------------
__global__ void __launch_bounds__(256) k_pre(const float* __restrict__ rule,
                                             const float* __restrict__ unary) {
    int blk = blockIdx.x;
    int h = blk % Nn;
    int a = (blk / Nn) % NTT;
    int b = blk / (Nn * NTT);
    const float2* R2 = (const float2*)(rule + (size_t)((b * NTT + a) * Nn + h) * (TT * TT * 2));

    __shared__ float Er0[TT][TT];
    __shared__ float Er1[TT][TT];
    __shared__ float eus[Nn][49];
    int tid = threadIdx.x;

    for (int e = tid; e < TT * TT; e += 256) {
        float2 v = R2[e];
        int s = e >> 6, c = e & 63;
        Er0[s][c] = __expf(v.x);
        Er1[s][c] = __expf(v.y);
    }
    for (int t = tid; t < Nn * TSS; t += 256) {
        int k = t / TSS, c = t % TSS;
        eus[k][c] = __expf(unary[(b * Nn + k) * TT + NTT + c]);
    }
    __syncthreads();

    // E tables (NT x NT corner)
    {
        int s = tid >> 4, c = tid & 15;
        d_E0t[b][h][s][c][a] = Er0[s][c];
        d_E1t[b][h][s][c][a] = Er1[s][c];
    }
    // V tables
    if (tid < 128) {
        int x = tid & 63;
        float acc = 0.f;
        if (tid < 64) {
            #pragma unroll 8
            for (int s = NTT; s < TT; s++) acc += Er0[s][x];
            d_V0t[b][h][x][a] = acc;
        } else {
            #pragma unroll 8
            for (int c = NTT; c < TT; c++) acc += Er1[x][c];
            d_V1t[b][h][x][a] = acc;
        }
    }
    // U tables, register-tiled 4x over k
    if (tid < 192) {
        int which = tid / 96;
        int g = tid % 96;
        int x = g & 15, k0 = (g >> 4) * 4;
        float a0 = 0.f, a1 = 0.f, a2 = 0.f, a3 = 0.f;
        if (which == 0) {
            #pragma unroll 8
            for (int c = 0; c < TSS; c++) {
                float e = Er0[x][NTT + c];
                a0 += e * eus[k0 + 0][c];
                a1 += e * eus[k0 + 1][c];
                a2 += e * eus[k0 + 2][c];
                a3 += e * eus[k0 + 3][c];
            }
            d_U0t[b][h][k0 + 0][x][a] = a0;
            d_U0t[b][h][k0 + 1][x][a] = a1;
            d_U0t[b][h][k0 + 2][x][a] = a2;
            d_U0t[b][h][k0 + 3][x][a] = a3;
        } else {
            #pragma unroll 8
            for (int s = 0; s < TSS; s++) {
                float e = Er1[NTT + s][x];
                a0 += e * eus[k0 + 0][s];
                a1 += e * eus[k0 + 1][s];
                a2 += e * eus[k0 + 2][s];
                a3 += e * eus[k0 + 3][s];
            }
            d_U1t[b][h][k0 + 0][x][a] = a0;
            d_U1t[b][h][k0 + 1][x][a] = a1;
            d_U1t[b][h][k0 + 2][x][a] = a2;
            d_U1t[b][h][k0 + 3][x][a] = a3;
        }
    }
}

// ---------------- grid barrier ----------------
__device__ __forceinline__ void grid_sync() {
    __syncthreads();
    if (threadIdx.x == 0) {
        __threadfence();
        int g = g_gen;
        if (atomicAdd(&g_cnt, 1) == GBLK - 1) {
            g_cnt = 0;
            __threadfence();
            g_gen = g + 1;
        } else {
            while (g_gen == g) { __nanosleep(64); }
        }
        __threadfence();
    }
    __syncthreads();
}

// ---------------- kernel 2: persistent chart kernel ----------------
__global__ void __launch_bounds__(THR, 1) k_chart(const float* __restrict__ unary,
                                                  const float* __restrict__ root,
                                                  float* __restrict__ out) {
    extern __shared__ float Psm[];        // [2][256][Wp], Wp = W|1
    __shared__ float eu_s[Nn][TT];
    __shared__ float buR[Nn][NTT];
    __shared__ float buL[Nn][NTT];
    __shared__ float BL2[NTT][Nn];
    __shared__ float BL3[NTT][Nn];
    __shared__ float wsp[Nn];
    __shared__ float tmpsm[NTT][Nn];
    __shared__ float Ppart[16][Nn][NTT];  // [part][hh][a]
    __shared__ float bu_fin[NTT];
    __shared__ float red[12];
    __shared__ float sref_s, Msm;

    int tid = threadIdx.x;
    int b = blockIdx.x / NL;
    int l = blockIdx.x % NL;

    for (int t = tid; t < Nn * TT; t += THR)
        (&eu_s[0][0])[t] = __expf(unary[b * Nn * TT + t]);
    __syncthreads();

    for (int W = 2; W <= Nn; W++) {
        if (l <= Nn - W) {
            int r = l + W;
            int nT = NTT * W;
            int Wp = W | 1;

            // ---- split-scale weights ----
            if (tid < W - 1) {
                int j = tid, m = l + 1 + j;
                float sl = (j == 0)     ? 0.f : __ldcg(&d_Ssc[b][l][m]);
                float sr = (j == W - 2) ? 0.f : __ldcg(&d_Ssc[b][m][r]);
                wsp[j] = sl + sr;
            }
            __syncthreads();
            if (tid == 0) {
                float s = -1e30f;
                for (int j = 0; j <= W - 2; j++) s = fmaxf(s, wsp[j]);
                sref_s = s;
            }
            __syncthreads();
            if (tid < W - 1) wsp[tid] = __expf(wsp[tid] - sref_s);
            __syncthreads();

            // ---- child charts into smem ----
            if (W >= 3) {
                if (tid < (W - 2) * NTT) {
                    int j = tid >> 4, c = tid & 15;
                    buR[j][c]     = wsp[j]     * __ldcg(&d_betau[b][l + 1 + j][r][c]);
                    buL[j + 1][c] = wsp[j + 1] * __ldcg(&d_betau[b][l][l + 2 + j][c]);
                }
                if (tid < nT) {
                    int c = tid / W, hh = tid % W;
                    BL2[c][hh] = __ldcg(&d_beta[b][l + 1][r][c][l + hh]);
                    BL3[c][hh] = __ldcg(&d_beta[b][l][r - 1][c][l + hh]);
                }
            }
            __syncthreads();

            float tacc = 0.f;
            float* P0 = Psm;
            float* P1 = Psm + 256 * Wp;

            if (W >= 4) {
                // ---- P build: chunk-4 dual-stream (zero-fill makes full j-range exact) ----
                if (tid < nT) {
                    int hh = tid % W, x = tid / W;
                    float av0[NTT], av1[NTT];
                    #pragma unroll
                    for (int c = 0; c < NTT; c++) { av0[c] = 0.f; av1[c] = 0.f; }
                    int j = 1;
                    for (; j + 3 <= W - 3; j += 4) {
                        float l0 = __ldcg(&d_beta[b][l][l + 1 + j][x][l + hh]);
                        float l1 = __ldcg(&d_beta[b][l][l + 2 + j][x][l + hh]);
                        float l2 = __ldcg(&d_beta[b][l][l + 3 + j][x][l + hh]);
                        float l3 = __ldcg(&d_beta[b][l][l + 4 + j][x][l + hh]);
                        float r0 = __ldcg(&d_beta[b][l + 1 + j][r][x][l + hh]);
                        float r1 = __ldcg(&d_beta[b][l + 2 + j][r][x][l + hh]);
                        float r2 = __ldcg(&d_beta[b][l + 3 + j][r][x][l + hh]);
                        float r3 = __ldcg(&d_beta[b][l + 4 + j][r][x][l + hh]);
                        #pragma unroll
                        for (int c = 0; c < NTT; c++) {
                            av0[c] += l0 * buR[j][c] + l1 * buR[j + 1][c]
                                    + l2 * buR[j + 2][c] + l3 * buR[j + 3][c];
                            av1[c] += r0 * buL[j][c] + r1 * buL[j + 1][c]
                                    + r2 * buL[j + 2][c] + r3 * buL[j + 3][c];
                        }
                    }
                    for (; j <= W - 3; j++) {
                        float bl = __ldcg(&d_beta[b][l][l + 1 + j][x][l + hh]);
                        float br = __ldcg(&d_beta[b][l + 1 + j][r][x][l + hh]);
                        #pragma unroll
                        for (int c = 0; c < NTT; c++) {
                            av0[c] += bl * buR[j][c];
                            av1[c] += br * buL[j][c];
                        }
                    }
                    #pragma unroll
                    for (int c = 0; c < NTT; c++) {
                        P0[(x * NTT + c) * Wp + hh] = av0[c];
                        P1[(c * NTT + x) * Wp + hh] = av1[c];
                    }
                }
                __syncthreads();

                // ---- contraction: float4 over a, sc split to fill ~384 threads ----
                int SPLIT = (W <= 6) ? 16 : ((W <= 12) ? 8 : 4);
                int CH = 256 / SPLIT;
                if (tid < 4 * W * SPLIT) {
                    int part = tid / (4 * W);
                    int rem  = tid - part * 4 * W;
                    int a4 = rem / W;
                    int hh = rem - a4 * W;
                    const float4* E0 = reinterpret_cast<const float4*>(d_E0t[b][l + hh][0][0]);
                    const float4* E1 = reinterpret_cast<const float4*>(d_E1t[b][l + hh][0][0]);
                    const float* p0 = P0 + hh;
                    const float* p1 = P1 + hh;
                    int base = part * CH;
                    float4 acc0 = make_float4(0.f, 0.f, 0.f, 0.f);
                    float4 acc1 = make_float4(0.f, 0.f, 0.f, 0.f);
                    #pragma unroll 8
                    for (int i = 0; i < CH; i++) {
                        int sc = base + i;
                        float v0 = p0[sc * Wp];
                        float v1 = p1[sc * Wp];
                        float4 e0 = __ldg(E0 + sc * 4 + a4);
                        float4 e1 = __ldg(E1 + sc * 4 + a4);
                        acc0.x += v0 * e0.x; acc0.y += v0 * e0.y;
                        acc0.z += v0 * e0.z; acc0.w += v0 * e0.w;
                        acc1.x += v1 * e1.x; acc1.y += v1 * e1.y;
                        acc1.z += v1 * e1.z; acc1.w += v1 * e1.w;
                    }
                    Ppart[part][hh][a4 * 4 + 0] = acc0.x + acc1.x;
                    Ppart[part][hh][a4 * 4 + 1] = acc0.y + acc1.y;
                    Ppart[part][hh][a4 * 4 + 2] = acc0.z + acc1.z;
                    Ppart[part][hh][a4 * 4 + 3] = acc0.w + acc1.w;
                }
                __syncthreads();
                if (tid < nT) {
                    int a = tid & 15, hh = tid >> 4;
                    float s = 0.f;
                    for (int k = 0; k < SPLIT; k++) s += Ppart[k][hh][a];
                    tacc += s;
                }
            }

            // ---- boundary (width-1 child) terms ----
            if (W >= 3) {
                if (tid < nT) {
                    int a = tid & 15, hh = tid >> 4;
                    const float* U1 = &d_U1t[b][l + hh][l][0][a];
                    const float* U0 = &d_U0t[b][l + hh][r - 1][0][a];
                    float s2 = 0.f, s3 = 0.f;
                    #pragma unroll
                    for (int c = 0; c < NTT; c++) {
                        s2 += __ldg(U1 + c * NTT) * BL2[c][hh];
                        s3 += __ldg(U0 + c * NTT) * BL3[c][hh];
                    }
                    tacc += wsp[0] * s2 + wsp[W - 2] * s3;
                    if (hh == 0) {
                        float s1 = 0.f;
                        #pragma unroll
                        for (int c = 0; c < NTT; c++)
                            s1 += __ldg(&d_V0t[b][l][c][a]) * buR[0][c];
                        tacc += s1;
                    }
                    if (hh == W - 1) {
                        float s4 = 0.f;
                        #pragma unroll
                        for (int c = 0; c < NTT; c++)
                            s4 += __ldg(&d_V1t[b][r - 1][c][a]) * buL[W - 2][c];
                        tacc += s4;
                    }
                }
            } else {  // W == 2
                if (tid < nT) {
                    int a = tid & 15, hh = tid >> 4;
                    float acc = 0.f;
                    if (hh == 0) {
                        #pragma unroll 8
                        for (int c = 0; c < TSS; c++)
                            acc += eu_s[l + 1][NTT + c] * __ldg(&d_V0t[b][l][NTT + c][a]);
                    } else {
                        #pragma unroll 8
                        for (int c = 0; c < TSS; c++)
                            acc += eu_s[l][NTT + c] * __ldg(&d_V1t[b][l + 1][NTT + c][a]);
                    }
                    tacc += acc;
                }
            }

            // ---- max, rescale, commit ----
            float vmax = 0.f;
            if (tid < nT) {
                int a = tid & 15, hh = tid >> 4;
                tmpsm[a][hh] = tacc;
                vmax = tacc;
            }
            #pragma unroll
            for (int o = 16; o > 0; o >>= 1) vmax = fmaxf(vmax, __shfl_xor_sync(0xffffffffu, vmax, o));
            if ((tid & 31) == 0) red[tid >> 5] = vmax;
            __syncthreads();
            if (tid < 32) {
                float v = (tid < 12) ? red[tid] : 0.f;
                #pragma unroll
                for (int o = 8; o > 0; o >>= 1) v = fmaxf(v, __shfl_xor_sync(0xffffffffu, v, o));
                if (tid == 0) { Msm = v; __stcg(&d_Ssc[b][l][r], sref_s + logf(v)); }
            }
            __syncthreads();
            float invM = 1.f / Msm;
            {
                int a = tid / Nn, habs = tid % Nn;   // THR == 16*24 exactly
                float v = 0.f;
                if (habs >= l && habs < r) v = tmpsm[a][habs - l] * invM;
                __stcg(&d_beta[b][l][r][a][habs], v);
            }
            if (tid < NTT) {
                float accu = 0.f;
                for (int hh = 0; hh < W; hh++)
                    accu += tmpsm[tid][hh] * eu_s[l + hh][tid];
                float bu = accu * invM;
                __stcg(&d_betau[b][l][r][tid], bu);
                if (W == Nn) bu_fin[tid] = bu;   // only block (b, 0) reaches W == Nn
            }

            // ---- root reduction (block (b,0), from its own smem) ----
            if (W == Nn) {
                __syncthreads();
                if (tid < NTT) {
                    float v = bu_fin[tid] * __expf(root[b * NTT + tid]);
                    #pragma unroll
                    for (int o = 8; o > 0; o >>= 1) v += __shfl_xor_sync(0xffffu, v, o);
                    if (tid == 0) out[b] = sref_s + logf(Msm) + logf(v);
                }
            }
        }
        if (W < Nn) grid_sync();
    }
}

// ---------------- launch ----------------
extern "C" void kernel_launch(void* const* d_in, const int* in_sizes, int n_in,
                              void* d_out, int out_size) {
    const float* unary = nullptr;
    const float* rule  = nullptr;
    const float* root  = nullptr;
    for (int i = 0; i < n_in; i++) {
        if (in_sizes[i] == Bv * Nn * TT)                      unary = (const float*)d_in[i];
        else if (in_sizes[i] == Bv * NTT * Nn * TT * TT * 2)  rule  = (const float*)d_in[i];
        else if (in_sizes[i] == Bv * NTT)                     root  = (const float*)d_in[i];
    }

    cudaFuncSetAttribute(k_chart, cudaFuncAttributeMaxDynamicSharedMemorySize, 2 * 256 * 25 * 4);

    k_pre<<<Bv * NTT * Nn, 256>>>(rule, unary);
    k_chart<<<GBLK, THR, 2 * 256 * 25 * sizeof(float)>>>(unary, root, (float*)d_out);
}

// round 5
// speedup vs baseline: 1.8378x; 1.7785x over previous
#include <cuda_runtime.h>
#include <math.h>

#define Bv  4
#define Nn  24
#define NTT 16
#define TSS 48
#define TT  64
#define THR 384
#define NL  (Nn - 1)          // 23 l-slots per batch

// ---------------- device scratch ----------------
__device__ __align__(16) float d_E0t [Bv][Nn][NTT][NTT][NTT];  // exp(R0) as [b][h][s][c][a]
__device__ __align__(16) float d_E1t [Bv][Nn][NTT][NTT][NTT];
__device__ float d_U0t [Bv][Nn][Nn][NTT][NTT];       // [b][h][k][s][a]
__device__ float d_U1t [Bv][Nn][Nn][NTT][NTT];       // [b][h][k][c][a]
__device__ float d_V0t [Bv][Nn][TT][NTT];            // [b][h][c][a]
__device__ float d_V1t [Bv][Nn][TT][NTT];            // [b][h][s][a]
__device__ float d_beta [Bv][Nn+1][Nn+1][NTT][Nn];
__device__ float d_betau[Bv][Nn+1][Nn+1][NTT];
__device__ float d_Ssc  [Bv][Nn+1][Nn+1];
__device__ volatile unsigned d_flag[Bv][Nn+1][Nn+1];

// ---------------- kernel 1: rule precompute + flag reset ----------------
__global__ void __launch_bounds__(256) k_pre(const float* __restrict__ rule,
                                             const float* __restrict__ unary) {
    int blk = blockIdx.x;
    int h = blk % Nn;
    int a = (blk / Nn) % NTT;
    int b = blk / (Nn * NTT);
    const float2* R2 = (const float2*)(rule + (size_t)((b * NTT + a) * Nn + h) * (TT * TT * 2));

    __shared__ float Er0[TT][TT];
    __shared__ float Er1[TT][TT];
    __shared__ float eus[Nn][49];
    int tid = threadIdx.x;

    if (blk == 0) {  // reset dataflow flags for this replay (stream-ordered before k_chart)
        for (int i = tid; i < Bv * (Nn + 1) * (Nn + 1); i += 256)
            ((unsigned*)d_flag)[i] = 0;
    }

    for (int e = tid; e < TT * TT; e += 256) {
        float2 v = R2[e];
        int s = e >> 6, c = e & 63;
        Er0[s][c] = __expf(v.x);
        Er1[s][c] = __expf(v.y);
    }
    for (int t = tid; t < Nn * TSS; t += 256) {
        int k = t / TSS, c = t % TSS;
        eus[k][c] = __expf(unary[(b * Nn + k) * TT + NTT + c]);
    }
    __syncthreads();

    {
        int s = tid >> 4, c = tid & 15;
        d_E0t[b][h][s][c][a] = Er0[s][c];
        d_E1t[b][h][s][c][a] = Er1[s][c];
    }
    if (tid < 128) {
        int x = tid & 63;
        float acc = 0.f;
        if (tid < 64) {
            #pragma unroll 8
            for (int s = NTT; s < TT; s++) acc += Er0[s][x];
            d_V0t[b][h][x][a] = acc;
        } else {
            #pragma unroll 8
            for (int c = NTT; c < TT; c++) acc += Er1[x][c];
            d_V1t[b][h][x][a] = acc;
        }
    }
    if (tid < 192) {
        int which = tid / 96;
        int g = tid % 96;
        int x = g & 15, k0 = (g >> 4) * 4;
        float a0 = 0.f, a1 = 0.f, a2 = 0.f, a3 = 0.f;
        if (which == 0) {
            #pragma unroll 8
            for (int c = 0; c < TSS; c++) {
                float e = Er0[x][NTT + c];
                a0 += e * eus[k0 + 0][c];
                a1 += e * eus[k0 + 1][c];
                a2 += e * eus[k0 + 2][c];
                a3 += e * eus[k0 + 3][c];
            }
            d_U0t[b][h][k0 + 0][x][a] = a0;
            d_U0t[b][h][k0 + 1][x][a] = a1;
            d_U0t[b][h][k0 + 2][x][a] = a2;
            d_U0t[b][h][k0 + 3][x][a] = a3;
        } else {
            #pragma unroll 8
            for (int s = 0; s < TSS; s++) {
                float e = Er1[NTT + s][x];
                a0 += e * eus[k0 + 0][s];
                a1 += e * eus[k0 + 1][s];
                a2 += e * eus[k0 + 2][s];
                a3 += e * eus[k0 + 3][s];
            }
            d_U1t[b][h][k0 + 0][x][a] = a0;
            d_U1t[b][h][k0 + 1][x][a] = a1;
            d_U1t[b][h][k0 + 2][x][a] = a2;
            d_U1t[b][h][k0 + 3][x][a] = a3;
        }
    }
}

// ---------------- kernel 2: dataflow chart kernel ----------------
__global__ void __launch_bounds__(THR, 1) k_chart(const float* __restrict__ unary,
                                                  const float* __restrict__ root,
                                                  float* __restrict__ out) {
    extern __shared__ float Psm[];                 // [2][256][Wp]
    __shared__ float eu_s[Nn][TT];
    __shared__ float buR[Nn][NTT];
    __shared__ float buL[Nn][NTT];
    __shared__ __align__(16) float wRT0[NTT][24];  // [c][jj], jj = j-1, zero-padded
    __shared__ __align__(16) float wRT1[NTT][24];
    __shared__ float BL2[NTT][Nn];
    __shared__ float BL3[NTT][Nn];
    __shared__ float wsp[Nn];
    __shared__ float tmpsm[NTT][Nn];
    __shared__ float red[12];
    __shared__ float sref_s, Msm;

    int tid = threadIdx.x;
    int b = blockIdx.x / NL;
    int l = blockIdx.x % NL;

    for (int t = tid; t < Nn * TT; t += THR)
        (&eu_s[0][0])[t] = __expf(unary[b * Nn * TT + t]);
    __syncthreads();

    int Wmax = Nn - l;
    for (int W = 2; W <= Wmax; W++) {
        int r = l + W;
        int nT = NTT * W;
        int Wp = W | 1;

        // ---- warp 0: wait for right-edge children, then split-scale weights ----
        if (tid < 32) {
            if (W >= 3 && tid < W - 2) {
                while (d_flag[b][l + 1 + tid][r] == 0) __nanosleep(32);
            }
            __threadfence();   // acquire
            float v = -1e30f;
            if (tid <= W - 2) {
                int m = l + 1 + tid;
                float sl = (tid == 0)     ? 0.f : __ldcg(&d_Ssc[b][l][m]);
                float sr = (tid == W - 2) ? 0.f : __ldcg(&d_Ssc[b][m][r]);
                v = sl + sr;
            }
            float mx = v;
            #pragma unroll
            for (int o = 16; o > 0; o >>= 1) mx = fmaxf(mx, __shfl_xor_sync(0xffffffffu, mx, o));
            if (tid <= W - 2) wsp[tid] = __expf(v - mx);
            if (tid == 0) sref_s = mx;
        }
        __syncthreads();

        // ---- child charts into smem ----
        if (W >= 3) {
            if (tid < (W - 2) * NTT) {
                int j = tid >> 4, c = tid & 15;
                buR[j][c]     = wsp[j]     * __ldcg(&d_betau[b][l + 1 + j][r][c]);
                buL[j + 1][c] = wsp[j + 1] * __ldcg(&d_betau[b][l][l + 2 + j][c]);
            }
            if (tid < nT) {
                int c = tid / W, hh = tid % W;
                BL2[c][hh] = __ldcg(&d_beta[b][l + 1][r][c][l + hh]);
                BL3[c][hh] = __ldcg(&d_beta[b][l][r - 1][c][l + hh]);
            }
        }
        __syncthreads();

        float* P0 = Psm;
        float* P1 = Psm + 256 * Wp;

        if (W >= 4) {
            // ---- transposed, zero-padded weight tables (jj = j-1, j in [1, W-3]) ----
            for (int t = tid; t < NTT * 24; t += THR) {
                int c = t / 24, jj = t % 24;
                int j = jj + 1;
                bool in = (j <= W - 3);
                wRT0[c][jj] = in ? buR[j][c] : 0.f;
                wRT1[c][jj] = in ? buL[j][c] : 0.f;
            }
            __syncthreads();

            // ---- P build: all betas upfront (MLP ~42), c-outer FMA vs float4 tables ----
            if (tid < nT) {
                int hh = tid % W, x = tid / W;   // hh fastest in lane -> coalesced beta loads
                float bvL[21], bvR[21];
                #pragma unroll
                for (int j = 1; j <= 21; j++) {
                    bool in = (j <= W - 3);
                    bvL[j - 1] = in ? __ldcg(&d_beta[b][l][l + 1 + j][x][l + hh]) : 0.f;
                    bvR[j - 1] = in ? __ldcg(&d_beta[b][l + 1 + j][r][x][l + hh]) : 0.f;
                }
                #pragma unroll
                for (int c = 0; c < NTT; c++) {
                    float a0 = 0.f, a1 = 0.f;
                    #pragma unroll
                    for (int k = 0; k < 6; k++) {
                        if (4 * k <= W - 4) {   // warp-uniform (W uniform)
                            float4 w0 = *(const float4*)&wRT0[c][4 * k];
                            float4 w1 = *(const float4*)&wRT1[c][4 * k];
                            a0 = fmaf(bvL[4 * k + 0], w0.x, a0);
                            a0 = fmaf(bvL[4 * k + 1], w0.y, a0);
                            a0 = fmaf(bvL[4 * k + 2], w0.z, a0);
                            a0 = fmaf(bvL[4 * k + 3], w0.w, a0);
                            a1 = fmaf(bvR[4 * k + 0], w1.x, a1);
                            a1 = fmaf(bvR[4 * k + 1], w1.y, a1);
                            a1 = fmaf(bvR[4 * k + 2], w1.z, a1);
                            a1 = fmaf(bvR[4 * k + 3], w1.w, a1);
                        }
                    }
                    P0[(x * NTT + c) * Wp + hh] = a0;
                    P1[(c * NTT + x) * Wp + hh] = a1;
                }
            }
            __syncthreads();

            // ---- contraction: warp per hh, lanes = (sc_lo, a4) -> coalesced E loads ----
            {
                int wid = tid >> 5, lane = tid & 31;
                int sc_lo = lane >> 2, a4 = lane & 3;
                for (int hh = wid; hh < W; hh += 12) {
                    const float4* E0 = reinterpret_cast<const float4*>(d_E0t[b][l + hh][0][0]);
                    const float4* E1 = reinterpret_cast<const float4*>(d_E1t[b][l + hh][0][0]);
                    const float* p0 = P0 + hh;
                    const float* p1 = P1 + hh;
                    float4 s0 = make_float4(0.f, 0.f, 0.f, 0.f);
                    float4 s1 = make_float4(0.f, 0.f, 0.f, 0.f);
                    #pragma unroll 8
                    for (int sc0 = 0; sc0 < 256; sc0 += 8) {
                        int sc = sc0 + sc_lo;
                        float v0 = p0[sc * Wp];
                        float v1 = p1[sc * Wp];
                        float4 e0 = __ldg(E0 + sc * 4 + a4);
                        float4 e1 = __ldg(E1 + sc * 4 + a4);
                        s0.x = fmaf(v0, e0.x, s0.x); s0.y = fmaf(v0, e0.y, s0.y);
                        s0.z = fmaf(v0, e0.z, s0.z); s0.w = fmaf(v0, e0.w, s0.w);
                        s1.x = fmaf(v1, e1.x, s1.x); s1.y = fmaf(v1, e1.y, s1.y);
                        s1.z = fmaf(v1, e1.z, s1.z); s1.w = fmaf(v1, e1.w, s1.w);
                    }
                    float4 s;
                    s.x = s0.x + s1.x; s.y = s0.y + s1.y;
                    s.z = s0.z + s1.z; s.w = s0.w + s1.w;
                    #pragma unroll
                    for (int o = 4; o <= 16; o <<= 1) {
                        s.x += __shfl_xor_sync(0xffffffffu, s.x, o);
                        s.y += __shfl_xor_sync(0xffffffffu, s.y, o);
                        s.z += __shfl_xor_sync(0xffffffffu, s.z, o);
                        s.w += __shfl_xor_sync(0xffffffffu, s.w, o);
                    }
                    if (sc_lo == 0) {
                        tmpsm[a4 * 4 + 0][hh] = s.x;
                        tmpsm[a4 * 4 + 1][hh] = s.y;
                        tmpsm[a4 * 4 + 2][hh] = s.z;
                        tmpsm[a4 * 4 + 3][hh] = s.w;
                    }
                }
            }
            __syncthreads();
        }

        // ---- boundary terms + assemble tval ----
        float tval = 0.f;
        if (tid < nT) {
            int a = tid & 15, hh = tid >> 4;
            if (W >= 4) tval = tmpsm[a][hh];
            if (W >= 3) {
                const float* U1 = &d_U1t[b][l + hh][l][0][a];
                const float* U0 = &d_U0t[b][l + hh][r - 1][0][a];
                float s2 = 0.f, s3 = 0.f;
                #pragma unroll
                for (int c = 0; c < NTT; c++) {
                    s2 += __ldg(U1 + c * NTT) * BL2[c][hh];
                    s3 += __ldg(U0 + c * NTT) * BL3[c][hh];
                }
                tval += wsp[0] * s2 + wsp[W - 2] * s3;
                if (hh == 0) {
                    float s1 = 0.f;
                    #pragma unroll
                    for (int c = 0; c < NTT; c++)
                        s1 += __ldg(&d_V0t[b][l][c][a]) * buR[0][c];
                    tval += s1;
                }
                if (hh == W - 1) {
                    float s4 = 0.f;
                    #pragma unroll
                    for (int c = 0; c < NTT; c++)
                        s4 += __ldg(&d_V1t[b][r - 1][c][a]) * buL[W - 2][c];
                    tval += s4;
                }
            } else {  // W == 2
                if (hh == 0) {
                    #pragma unroll 8
                    for (int c = 0; c < TSS; c++)
                        tval += eu_s[l + 1][NTT + c] * __ldg(&d_V0t[b][l][NTT + c][a]);
                } else {
                    #pragma unroll 8
                    for (int c = 0; c < TSS; c++)
                        tval += eu_s[l][NTT + c] * __ldg(&d_V1t[b][l + 1][NTT + c][a]);
                }
            }
        }

        // ---- max, rescale, commit, publish ----
        float vmax = 0.f;
        if (tid < nT) {
            int a = tid & 15, hh = tid >> 4;
            tmpsm[a][hh] = tval;
            vmax = tval;
        }
        #pragma unroll
        for (int o = 16; o > 0; o >>= 1) vmax = fmaxf(vmax, __shfl_xor_sync(0xffffffffu, vmax, o));
        if ((tid & 31) == 0) red[tid >> 5] = vmax;
        __syncthreads();
        if (tid < 32) {
            float v = (tid < 12) ? red[tid] : 0.f;
            #pragma unroll
            for (int o = 8; o > 0; o >>= 1) v = fmaxf(v, __shfl_xor_sync(0xffffffffu, v, o));
            if (tid == 0) { Msm = v; __stcg(&d_Ssc[b][l][r], sref_s + logf(v)); }
        }
        __syncthreads();
        float invM = 1.f / Msm;
        {
            int a = tid / Nn, habs = tid % Nn;   // THR == 16*24 exactly
            float v = 0.f;
            if (habs >= l && habs < r) v = tmpsm[a][habs - l] * invM;
            __stcg(&d_beta[b][l][r][a][habs], v);
        }
        if (tid < NTT) {
            float accu = 0.f;
            for (int hh = 0; hh < W; hh++)
                accu += tmpsm[tid][hh] * eu_s[l + hh][tid];
            float bu = accu * invM;
            __stcg(&d_betau[b][l][r][tid], bu);
            // root reduction fused into the last cell of block (b, 0)
            if (W == Nn) {
                float v = bu * __expf(root[b * NTT + tid]);
                #pragma unroll
                for (int o = 8; o > 0; o >>= 1) v += __shfl_xor_sync(0xffffu, v, o);
                if (tid == 0) out[b] = sref_s + logf(Msm) + logf(v);
            }
        }
        __threadfence();   // release
        __syncthreads();
        if (tid == 0) d_flag[b][l][r] = 1;
    }
}

// ---------------- launch ----------------
extern "C" void kernel_launch(void* const* d_in, const int* in_sizes, int n_in,
                              void* d_out, int out_size) {
    const float* unary = nullptr;
    const float* rule  = nullptr;
    const float* root  = nullptr;
    for (int i = 0; i < n_in; i++) {
        if (in_sizes[i] == Bv * Nn * TT)                      unary = (const float*)d_in[i];
        else if (in_sizes[i] == Bv * NTT * Nn * TT * TT * 2)  rule  = (const float*)d_in[i];
        else if (in_sizes[i] == Bv * NTT)                     root  = (const float*)d_in[i];
    }

    cudaFuncSetAttribute(k_chart, cudaFuncAttributeMaxDynamicSharedMemorySize,
                         2 * 256 * 25 * (int)sizeof(float));

    k_pre<<<Bv * NTT * Nn, 256>>>(rule, unary);
    k_chart<<<Bv * NL, THR, 2 * 256 * 25 * sizeof(float)>>>(unary, root, (float*)d_out);
}